// round 2
// baseline (speedup 1.0000x reference)
#include <cuda_runtime.h>

#define NN 100000
#define EE 1600000
#define FULLMASK 0xffffffffu

// Scratch (static __device__ arrays per harness rules)
__device__ int   g_cnt[NN];
__device__ int   g_rowptr[NN + 1];
__device__ int   g_cursor[NN];
__device__ int   g_col[EE];
__device__ int   g_bsum[256];
__device__ int   g_boff[256];
__device__ float g_dinv[NN];
__device__ float g_xd[NN];
__device__ float g_p1[NN * 64];
__device__ float g_a2[NN * 64];

__global__ void k_zero() {
    int i = blockIdx.x * blockDim.x + threadIdx.x;
    if (i < NN) g_cnt[i] = 0;
}

__global__ void k_count(const int* __restrict__ ei) {
    int e = blockIdx.x * blockDim.x + threadIdx.x;
    if (e < EE) {
        int dst = ei[EE + e];
        atomicAdd(&g_cnt[dst], 1);
    }
}

// ---- 3-kernel deterministic exclusive scan over g_cnt (250 blocks x 400 elems) ----
__global__ void k_scanA() {
    __shared__ int ws[16];
    int b = blockIdx.x, tid = threadIdx.x;
    int i = b * 400 + tid;
    int v = (tid < 400) ? g_cnt[i] : 0;
    for (int o = 16; o; o >>= 1) v += __shfl_xor_sync(FULLMASK, v, o);
    int lane = tid & 31, wid = tid >> 5;
    if (lane == 0) ws[wid] = v;
    __syncthreads();
    if (tid == 0) {
        int s = 0;
        for (int w = 0; w < 16; w++) s += ws[w];
        g_bsum[b] = s;
    }
}

__global__ void k_scanB() {
    __shared__ int ws[8];
    int tid = threadIdx.x;
    int v = (tid < 250) ? g_bsum[tid] : 0;
    int lane = tid & 31, wid = tid >> 5;
    int xv = v;
    for (int d = 1; d < 32; d <<= 1) {
        int n = __shfl_up_sync(FULLMASK, xv, d);
        if (lane >= d) xv += n;
    }
    if (lane == 31) ws[wid] = xv;
    __syncthreads();
    if (wid == 0 && lane < 8) {
        int w = ws[lane];
        for (int d = 1; d < 8; d <<= 1) {
            int n = __shfl_up_sync(0xffu, w, d);
            if (lane >= d) w += n;
        }
        ws[lane] = w;
    }
    __syncthreads();
    int off = (wid > 0) ? ws[wid - 1] : 0;
    int excl = off + xv - v;
    if (tid < 250) g_boff[tid] = excl;
    if (tid == 0) g_rowptr[NN] = EE;
}

__global__ void k_scanC(const float* __restrict__ x) {
    __shared__ int ws[16];
    int b = blockIdx.x, tid = threadIdx.x;
    int i = b * 400 + tid;
    int v = (tid < 400) ? g_cnt[i] : 0;
    int lane = tid & 31, wid = tid >> 5;
    int xc = v;
    for (int d = 1; d < 32; d <<= 1) {
        int n = __shfl_up_sync(FULLMASK, xc, d);
        if (lane >= d) xc += n;
    }
    if (lane == 31) ws[wid] = xc;
    __syncthreads();
    if (wid == 0) {
        int w = (lane < 16) ? ws[lane] : 0;
        for (int d = 1; d < 16; d <<= 1) {
            int n = __shfl_up_sync(FULLMASK, w, d);
            if (lane >= d) w += n;
        }
        if (lane < 16) ws[lane] = w;
    }
    __syncthreads();
    int excl = ((wid > 0) ? ws[wid - 1] : 0) + xc - v + g_boff[b];
    if (tid < 400) {
        g_rowptr[i] = excl;
        g_cursor[i] = excl;
        float dv = rsqrtf((float)(v + 1));   // deg includes self-loop
        g_dinv[i] = dv;
        g_xd[i]   = x[i] * dv;
    }
}

__global__ void k_fill(const int* __restrict__ ei) {
    int e = blockIdx.x * blockDim.x + threadIdx.x;
    if (e < EE) {
        int src = ei[e];
        int dst = ei[EE + e];
        int p = atomicAdd(&g_cursor[dst], 1);
        g_col[p] = src;
    }
}

__device__ __forceinline__ float silu_f(float v) {
    return v / (1.0f + __expf(-v));
}

// Layer 1: scalar gather + feature expansion; writes p1 = silu(a1*W1+b1)*dinv
__global__ void k_l1(const float* __restrict__ W1, const float* __restrict__ b1) {
    int w = (blockIdx.x * blockDim.x + threadIdx.x) >> 5;
    int lane = threadIdx.x & 31;
    if (w >= NN) return;
    int d = w;
    int s0 = g_rowptr[d], s1 = g_rowptr[d + 1];
    float s = 0.f;
    for (int j = s0 + lane; j < s1; j += 32) s += g_xd[g_col[j]];
    for (int o = 16; o; o >>= 1) s += __shfl_xor_sync(FULLMASK, s, o);
    float dv = g_dinv[d];
    float a1 = (s + g_xd[d]) * dv;   // self-loop term: xd[d]
    float h0 = fmaf(a1, W1[lane],      b1[lane]);
    float h1 = fmaf(a1, W1[lane + 32], b1[lane + 32]);
    h0 = silu_f(h0);
    h1 = silu_f(h1);
    g_p1[(d << 6) + lane]      = h0 * dv;
    g_p1[(d << 6) + lane + 32] = h1 * dv;
}

// Layer 2: 64-dim gather-aggregate (L2-resident rows), no float atomics
__global__ void k_l2() {
    int w = (blockIdx.x * blockDim.x + threadIdx.x) >> 5;
    int lane = threadIdx.x & 31;
    if (w >= NN) return;
    int d = w;
    const float2* __restrict__ p = (const float2*)g_p1;
    int base = d << 5;              // float2 row offset
    float2 acc = p[base + lane];    // self-loop term p1[d]
    int j = g_rowptr[d], e = g_rowptr[d + 1];
    for (; j + 4 <= e; j += 4) {
        int c0 = g_col[j], c1 = g_col[j + 1], c2 = g_col[j + 2], c3 = g_col[j + 3];
        float2 v0 = p[(c0 << 5) + lane];
        float2 v1 = p[(c1 << 5) + lane];
        float2 v2 = p[(c2 << 5) + lane];
        float2 v3 = p[(c3 << 5) + lane];
        acc.x += (v0.x + v1.x) + (v2.x + v3.x);
        acc.y += (v0.y + v1.y) + (v2.y + v3.y);
    }
    for (; j < e; j++) {
        float2 v = p[(g_col[j] << 5) + lane];
        acc.x += v.x;
        acc.y += v.y;
    }
    float dv = g_dinv[d];
    ((float2*)g_a2)[base + lane] = make_float2(acc.x * dv, acc.y * dv);
}

// Fused MLP head: a2 @ W2 + b2 -> silu -> @ W3 + b3 -> silu -> @ W4 + b4
__global__ void __launch_bounds__(256) k_mlp(
    const float* __restrict__ W2, const float* __restrict__ b2,
    const float* __restrict__ W3, const float* __restrict__ b3,
    const float* __restrict__ W4, const float* __restrict__ b4,
    float* __restrict__ out)
{
    __shared__ float2 sW2[64][32];
    __shared__ float2 sW3[64][32];
    __shared__ float  sW4[64];
    int tid = threadIdx.x;
    for (int idx = tid; idx < 64 * 32; idx += 256) {
        int k = idx >> 5, l = idx & 31;
        sW2[k][l] = make_float2(W2[k * 64 + l], W2[k * 64 + l + 32]);
        sW3[k][l] = make_float2(W3[k * 64 + l], W3[k * 64 + l + 32]);
    }
    if (tid < 64) sW4[tid] = W4[tid];
    __syncthreads();

    int lane = tid & 31;
    float2 rb2 = make_float2(b2[lane], b2[lane + 32]);
    float2 rb3 = make_float2(b3[lane], b3[lane + 32]);
    float w4lo = sW4[lane], w4hi = sW4[lane + 32];
    float b4v = b4[0];

    int warpG = (blockIdx.x * blockDim.x + tid) >> 5;
    int warpT = (gridDim.x * blockDim.x) >> 5;

    for (int d = warpG; d < NN; d += warpT) {
        float lo = g_a2[(d << 6) + lane];
        float hi = g_a2[(d << 6) + lane + 32];

        // GEMV 1: t @ W2 + b2
        float2 acc = rb2;
#pragma unroll
        for (int k = 0; k < 32; k++) {
            float t = __shfl_sync(FULLMASK, lo, k);
            float2 wv = sW2[k][lane];
            acc.x = fmaf(t, wv.x, acc.x);
            acc.y = fmaf(t, wv.y, acc.y);
        }
#pragma unroll
        for (int k = 0; k < 32; k++) {
            float t = __shfl_sync(FULLMASK, hi, k);
            float2 wv = sW2[k + 32][lane];
            acc.x = fmaf(t, wv.x, acc.x);
            acc.y = fmaf(t, wv.y, acc.y);
        }
        lo = silu_f(acc.x);
        hi = silu_f(acc.y);

        // GEMV 2: h @ W3 + b3
        acc = rb3;
#pragma unroll
        for (int k = 0; k < 32; k++) {
            float t = __shfl_sync(FULLMASK, lo, k);
            float2 wv = sW3[k][lane];
            acc.x = fmaf(t, wv.x, acc.x);
            acc.y = fmaf(t, wv.y, acc.y);
        }
#pragma unroll
        for (int k = 0; k < 32; k++) {
            float t = __shfl_sync(FULLMASK, hi, k);
            float2 wv = sW3[k + 32][lane];
            acc.x = fmaf(t, wv.x, acc.x);
            acc.y = fmaf(t, wv.y, acc.y);
        }
        lo = silu_f(acc.x);
        hi = silu_f(acc.y);

        // Output: dot with W4
        float part = lo * w4lo + hi * w4hi;
        for (int o = 16; o; o >>= 1) part += __shfl_xor_sync(FULLMASK, part, o);
        if (lane == 0) out[d] = part + b4v;
    }
}

extern "C" void kernel_launch(void* const* d_in, const int* in_sizes, int n_in,
                              void* d_out, int out_size) {
    const float* x  = (const float*)d_in[0];
    const int*   ei = (const int*)d_in[1];
    const float* W1 = (const float*)d_in[2];
    const float* b1 = (const float*)d_in[3];
    const float* W2 = (const float*)d_in[4];
    const float* b2 = (const float*)d_in[5];
    const float* W3 = (const float*)d_in[6];
    const float* b3 = (const float*)d_in[7];
    const float* W4 = (const float*)d_in[8];
    const float* b4 = (const float*)d_in[9];
    float* out = (float*)d_out;

    k_zero <<<(NN + 255) / 256, 256>>>();
    k_count<<<(EE + 255) / 256, 256>>>(ei);
    k_scanA<<<250, 512>>>();
    k_scanB<<<1, 256>>>();
    k_scanC<<<250, 512>>>(x);
    k_fill <<<(EE + 255) / 256, 256>>>(ei);
    k_l1   <<<(NN + 7) / 8, 256>>>(W1, b1);
    k_l2   <<<(NN + 7) / 8, 256>>>();
    k_mlp  <<<592, 256>>>(W2, b2, W3, b3, W4, b4, out);
}

// round 3
// speedup vs baseline: 1.3569x; 1.3569x over previous
#include <cuda_runtime.h>

#define NN 100000
#define EE 1600000
#define FULLMASK 0xffffffffu

// Scratch (static __device__ arrays per harness rules)
__device__ int   g_cnt[NN];
__device__ int   g_rowptr[NN + 1];
__device__ int   g_cursor[NN];
__device__ int   g_col[EE];
__device__ int   g_bsum[256];
__device__ int   g_boff[256];
__device__ float g_dinv[NN];
__device__ float g_xd[NN];
__device__ float g_p1[NN * 64];
__device__ float g_a2[NN * 64];

__global__ void k_zero() {
    int i = blockIdx.x * blockDim.x + threadIdx.x;
    if (i < NN) g_cnt[i] = 0;
}

__global__ void k_count(const int* __restrict__ ei) {
    int e = blockIdx.x * blockDim.x + threadIdx.x;
    if (e < EE) {
        int dst = ei[EE + e];
        atomicAdd(&g_cnt[dst], 1);
    }
}

// ---- 3-kernel deterministic exclusive scan over g_cnt (250 blocks x 400 elems) ----
__global__ void k_scanA() {
    __shared__ int ws[16];
    int b = blockIdx.x, tid = threadIdx.x;
    int i = b * 400 + tid;
    int v = (tid < 400) ? g_cnt[i] : 0;
    for (int o = 16; o; o >>= 1) v += __shfl_xor_sync(FULLMASK, v, o);
    int lane = tid & 31, wid = tid >> 5;
    if (lane == 0) ws[wid] = v;
    __syncthreads();
    if (tid == 0) {
        int s = 0;
        for (int w = 0; w < 16; w++) s += ws[w];
        g_bsum[b] = s;
    }
}

__global__ void k_scanB() {
    __shared__ int ws[8];
    int tid = threadIdx.x;
    int v = (tid < 250) ? g_bsum[tid] : 0;
    int lane = tid & 31, wid = tid >> 5;
    int xv = v;
    for (int d = 1; d < 32; d <<= 1) {
        int n = __shfl_up_sync(FULLMASK, xv, d);
        if (lane >= d) xv += n;
    }
    if (lane == 31) ws[wid] = xv;
    __syncthreads();
    if (wid == 0 && lane < 8) {
        int w = ws[lane];
        for (int d = 1; d < 8; d <<= 1) {
            int n = __shfl_up_sync(0xffu, w, d);
            if (lane >= d) w += n;
        }
        ws[lane] = w;
    }
    __syncthreads();
    int off = (wid > 0) ? ws[wid - 1] : 0;
    int excl = off + xv - v;
    if (tid < 250) g_boff[tid] = excl;
    if (tid == 0) g_rowptr[NN] = EE;
}

__global__ void k_scanC(const float* __restrict__ x) {
    __shared__ int ws[16];
    int b = blockIdx.x, tid = threadIdx.x;
    int i = b * 400 + tid;
    int v = (tid < 400) ? g_cnt[i] : 0;
    int lane = tid & 31, wid = tid >> 5;
    int xc = v;
    for (int d = 1; d < 32; d <<= 1) {
        int n = __shfl_up_sync(FULLMASK, xc, d);
        if (lane >= d) xc += n;
    }
    if (lane == 31) ws[wid] = xc;
    __syncthreads();
    if (wid == 0) {
        int w = (lane < 16) ? ws[lane] : 0;
        for (int d = 1; d < 16; d <<= 1) {
            int n = __shfl_up_sync(FULLMASK, w, d);
            if (lane >= d) w += n;
        }
        if (lane < 16) ws[lane] = w;
    }
    __syncthreads();
    int excl = ((wid > 0) ? ws[wid - 1] : 0) + xc - v + g_boff[b];
    if (tid < 400) {
        g_rowptr[i] = excl;
        g_cursor[i] = excl;
        float dv = rsqrtf((float)(v + 1));   // deg includes self-loop
        g_dinv[i] = dv;
        g_xd[i]   = x[i] * dv;
    }
}

__global__ void k_fill(const int* __restrict__ ei) {
    int e = blockIdx.x * blockDim.x + threadIdx.x;
    if (e < EE) {
        int src = ei[e];
        int dst = ei[EE + e];
        int p = atomicAdd(&g_cursor[dst], 1);
        g_col[p] = src;
    }
}

__device__ __forceinline__ float silu_f(float v) {
    return v / (1.0f + __expf(-v));
}

__device__ __forceinline__ unsigned long long pack2(float a, float b) {
    unsigned long long r;
    asm("mov.b64 %0, {%1, %2};" : "=l"(r) : "f"(a), "f"(b));
    return r;
}
__device__ __forceinline__ unsigned long long fma2(unsigned long long a,
                                                   unsigned long long b,
                                                   unsigned long long c) {
    unsigned long long d;
    asm("fma.rn.f32x2 %0, %1, %2, %3;" : "=l"(d) : "l"(a), "l"(b), "l"(c));
    return d;
}
__device__ __forceinline__ float2 unpack2(unsigned long long v) {
    float2 f;
    asm("mov.b64 {%0, %1}, %2;" : "=f"(f.x), "=f"(f.y) : "l"(v));
    return f;
}

// Layer 1: scalar gather + feature expansion; writes p1 = silu(a1*W1+b1)*dinv
__global__ void k_l1(const float* __restrict__ W1, const float* __restrict__ b1) {
    int w = (blockIdx.x * blockDim.x + threadIdx.x) >> 5;
    int lane = threadIdx.x & 31;
    if (w >= NN) return;
    int d = w;
    int s0 = g_rowptr[d], s1 = g_rowptr[d + 1];
    float s = 0.f;
    for (int j = s0 + lane; j < s1; j += 32) s += g_xd[g_col[j]];
    for (int o = 16; o; o >>= 1) s += __shfl_xor_sync(FULLMASK, s, o);
    float dv = g_dinv[d];
    float a1 = (s + g_xd[d]) * dv;   // self-loop term: xd[d]
    float h0 = fmaf(a1, W1[lane],      b1[lane]);
    float h1 = fmaf(a1, W1[lane + 32], b1[lane + 32]);
    h0 = silu_f(h0);
    h1 = silu_f(h1);
    g_p1[(d << 6) + lane]      = h0 * dv;
    g_p1[(d << 6) + lane + 32] = h1 * dv;
}

// Layer 2: 64-dim gather-aggregate (L2-resident rows), no float atomics
__global__ void k_l2() {
    int w = (blockIdx.x * blockDim.x + threadIdx.x) >> 5;
    int lane = threadIdx.x & 31;
    if (w >= NN) return;
    int d = w;
    const float2* __restrict__ p = (const float2*)g_p1;
    int base = d << 5;              // float2 row offset
    float2 acc = p[base + lane];    // self-loop term p1[d]
    int j = g_rowptr[d], e = g_rowptr[d + 1];
    for (; j + 4 <= e; j += 4) {
        int c0 = g_col[j], c1 = g_col[j + 1], c2 = g_col[j + 2], c3 = g_col[j + 3];
        float2 v0 = p[(c0 << 5) + lane];
        float2 v1 = p[(c1 << 5) + lane];
        float2 v2 = p[(c2 << 5) + lane];
        float2 v3 = p[(c3 << 5) + lane];
        acc.x += (v0.x + v1.x) + (v2.x + v3.x);
        acc.y += (v0.y + v1.y) + (v2.y + v3.y);
    }
    for (; j < e; j++) {
        float2 v = p[(g_col[j] << 5) + lane];
        acc.x += v.x;
        acc.y += v.y;
    }
    float dv = g_dinv[d];
    ((float2*)g_a2)[base + lane] = make_float2(acc.x * dv, acc.y * dv);
}

// Fused MLP head, M=4 nodes per warp, packed f32x2 FMA.
// acc[m] holds {out_j(lane), out_j+32(lane)} packed; weights pre-packed in smem.
__global__ void __launch_bounds__(256) k_mlp(
    const float* __restrict__ W2, const float* __restrict__ b2,
    const float* __restrict__ W3, const float* __restrict__ b3,
    const float* __restrict__ W4, const float* __restrict__ b4,
    float* __restrict__ out)
{
    __shared__ unsigned long long sW2[64][32];
    __shared__ unsigned long long sW3[64][32];
    int tid = threadIdx.x;
    for (int idx = tid; idx < 64 * 32; idx += 256) {
        int k = idx >> 5, l = idx & 31;
        sW2[k][l] = pack2(W2[k * 64 + l], W2[k * 64 + l + 32]);
        sW3[k][l] = pack2(W3[k * 64 + l], W3[k * 64 + l + 32]);
    }
    __syncthreads();

    int lane = tid & 31;
    unsigned long long rb2 = pack2(b2[lane], b2[lane + 32]);
    unsigned long long rb3 = pack2(b3[lane], b3[lane + 32]);
    float w4lo = W4[lane], w4hi = W4[lane + 32];
    float b4v = b4[0];

    int wg = (blockIdx.x * 256 + tid) >> 5;
    int wT = (gridDim.x * 256) >> 5;

    for (int g = wg; g < NN / 4; g += wT) {
        int d0 = g << 2;
        float lo[4], hi[4];
#pragma unroll
        for (int m = 0; m < 4; m++) {
            lo[m] = g_a2[((d0 + m) << 6) + lane];
            hi[m] = g_a2[((d0 + m) << 6) + lane + 32];
        }

        // ---- GEMV 1: a2 @ W2 + b2 ----
        unsigned long long acc0 = rb2, acc1 = rb2, acc2v = rb2, acc3 = rb2;
#pragma unroll
        for (int k = 0; k < 32; k++) {
            unsigned long long wv = sW2[k][lane];
            float t0 = __shfl_sync(FULLMASK, lo[0], k);
            float t1 = __shfl_sync(FULLMASK, lo[1], k);
            float t2 = __shfl_sync(FULLMASK, lo[2], k);
            float t3 = __shfl_sync(FULLMASK, lo[3], k);
            acc0 = fma2(pack2(t0, t0), wv, acc0);
            acc1 = fma2(pack2(t1, t1), wv, acc1);
            acc2v = fma2(pack2(t2, t2), wv, acc2v);
            acc3 = fma2(pack2(t3, t3), wv, acc3);
        }
#pragma unroll
        for (int k = 0; k < 32; k++) {
            unsigned long long wv = sW2[k + 32][lane];
            float t0 = __shfl_sync(FULLMASK, hi[0], k);
            float t1 = __shfl_sync(FULLMASK, hi[1], k);
            float t2 = __shfl_sync(FULLMASK, hi[2], k);
            float t3 = __shfl_sync(FULLMASK, hi[3], k);
            acc0 = fma2(pack2(t0, t0), wv, acc0);
            acc1 = fma2(pack2(t1, t1), wv, acc1);
            acc2v = fma2(pack2(t2, t2), wv, acc2v);
            acc3 = fma2(pack2(t3, t3), wv, acc3);
        }
        {
            float2 a0 = unpack2(acc0), a1 = unpack2(acc1),
                   a2f = unpack2(acc2v), a3 = unpack2(acc3);
            lo[0] = silu_f(a0.x); hi[0] = silu_f(a0.y);
            lo[1] = silu_f(a1.x); hi[1] = silu_f(a1.y);
            lo[2] = silu_f(a2f.x); hi[2] = silu_f(a2f.y);
            lo[3] = silu_f(a3.x); hi[3] = silu_f(a3.y);
        }

        // ---- GEMV 2: h @ W3 + b3 ----
        acc0 = rb3; acc1 = rb3; acc2v = rb3; acc3 = rb3;
#pragma unroll
        for (int k = 0; k < 32; k++) {
            unsigned long long wv = sW3[k][lane];
            float t0 = __shfl_sync(FULLMASK, lo[0], k);
            float t1 = __shfl_sync(FULLMASK, lo[1], k);
            float t2 = __shfl_sync(FULLMASK, lo[2], k);
            float t3 = __shfl_sync(FULLMASK, lo[3], k);
            acc0 = fma2(pack2(t0, t0), wv, acc0);
            acc1 = fma2(pack2(t1, t1), wv, acc1);
            acc2v = fma2(pack2(t2, t2), wv, acc2v);
            acc3 = fma2(pack2(t3, t3), wv, acc3);
        }
#pragma unroll
        for (int k = 0; k < 32; k++) {
            unsigned long long wv = sW3[k + 32][lane];
            float t0 = __shfl_sync(FULLMASK, hi[0], k);
            float t1 = __shfl_sync(FULLMASK, hi[1], k);
            float t2 = __shfl_sync(FULLMASK, hi[2], k);
            float t3 = __shfl_sync(FULLMASK, hi[3], k);
            acc0 = fma2(pack2(t0, t0), wv, acc0);
            acc1 = fma2(pack2(t1, t1), wv, acc1);
            acc2v = fma2(pack2(t2, t2), wv, acc2v);
            acc3 = fma2(pack2(t3, t3), wv, acc3);
        }
        {
            float2 a0 = unpack2(acc0), a1 = unpack2(acc1),
                   a2f = unpack2(acc2v), a3 = unpack2(acc3);
            lo[0] = silu_f(a0.x); hi[0] = silu_f(a0.y);
            lo[1] = silu_f(a1.x); hi[1] = silu_f(a1.y);
            lo[2] = silu_f(a2f.x); hi[2] = silu_f(a2f.y);
            lo[3] = silu_f(a3.x); hi[3] = silu_f(a3.y);
        }

        // ---- Output: dot with W4 ----
#pragma unroll
        for (int m = 0; m < 4; m++) {
            float part = lo[m] * w4lo + hi[m] * w4hi;
            for (int o = 16; o; o >>= 1) part += __shfl_xor_sync(FULLMASK, part, o);
            if (lane == 0) out[d0 + m] = part + b4v;
        }
    }
}

extern "C" void kernel_launch(void* const* d_in, const int* in_sizes, int n_in,
                              void* d_out, int out_size) {
    const float* x  = (const float*)d_in[0];
    const int*   ei = (const int*)d_in[1];
    const float* W1 = (const float*)d_in[2];
    const float* b1 = (const float*)d_in[3];
    const float* W2 = (const float*)d_in[4];
    const float* b2 = (const float*)d_in[5];
    const float* W3 = (const float*)d_in[6];
    const float* b3 = (const float*)d_in[7];
    const float* W4 = (const float*)d_in[8];
    const float* b4 = (const float*)d_in[9];
    float* out = (float*)d_out;

    k_zero <<<(NN + 255) / 256, 256>>>();
    k_count<<<(EE + 255) / 256, 256>>>(ei);
    k_scanA<<<250, 512>>>();
    k_scanB<<<1, 256>>>();
    k_scanC<<<250, 512>>>(x);
    k_fill <<<(EE + 255) / 256, 256>>>(ei);
    k_l1   <<<(NN + 7) / 8, 256>>>(W1, b1);
    k_l2   <<<(NN + 7) / 8, 256>>>();
    k_mlp  <<<888, 256>>>(W2, b2, W3, b3, W4, b4, out);
}

// round 4
// speedup vs baseline: 1.3648x; 1.0058x over previous
#include <cuda_runtime.h>

#define NN 100000
#define EE 1600000
#define FULLMASK 0xffffffffu

// Scratch (static __device__ arrays per harness rules)
__device__ int   g_cnt[NN];
__device__ int   g_rowptr[NN + 1];
__device__ int   g_cursor[NN];
__device__ int   g_col[EE];
__device__ int   g_bsum[256];
__device__ int   g_boff[256];
__device__ float g_dinv[NN];
__device__ float g_xd[NN];
__device__ float g_p1[NN * 64];   // layout: node d, lane l -> float2 {f_l, f_{l+32}} at ((float2*)g_p1)[d*32+l]

__global__ void k_zero() {
    int i = blockIdx.x * blockDim.x + threadIdx.x;
    if (i < NN) g_cnt[i] = 0;
}

__global__ void k_count(const int* __restrict__ ei) {
    int e = blockIdx.x * blockDim.x + threadIdx.x;
    if (e < EE) {
        int dst = ei[EE + e];
        atomicAdd(&g_cnt[dst], 1);
    }
}

// ---- 3-kernel deterministic exclusive scan over g_cnt (250 blocks x 400 elems) ----
__global__ void k_scanA() {
    __shared__ int ws[16];
    int b = blockIdx.x, tid = threadIdx.x;
    int i = b * 400 + tid;
    int v = (tid < 400) ? g_cnt[i] : 0;
    for (int o = 16; o; o >>= 1) v += __shfl_xor_sync(FULLMASK, v, o);
    int lane = tid & 31, wid = tid >> 5;
    if (lane == 0) ws[wid] = v;
    __syncthreads();
    if (tid == 0) {
        int s = 0;
        for (int w = 0; w < 16; w++) s += ws[w];
        g_bsum[b] = s;
    }
}

__global__ void k_scanB() {
    __shared__ int ws[8];
    int tid = threadIdx.x;
    int v = (tid < 250) ? g_bsum[tid] : 0;
    int lane = tid & 31, wid = tid >> 5;
    int xv = v;
    for (int d = 1; d < 32; d <<= 1) {
        int n = __shfl_up_sync(FULLMASK, xv, d);
        if (lane >= d) xv += n;
    }
    if (lane == 31) ws[wid] = xv;
    __syncthreads();
    if (wid == 0 && lane < 8) {
        int w = ws[lane];
        for (int d = 1; d < 8; d <<= 1) {
            int n = __shfl_up_sync(0xffu, w, d);
            if (lane >= d) w += n;
        }
        ws[lane] = w;
    }
    __syncthreads();
    int off = (wid > 0) ? ws[wid - 1] : 0;
    int excl = off + xv - v;
    if (tid < 250) g_boff[tid] = excl;
    if (tid == 0) g_rowptr[NN] = EE;
}

__global__ void k_scanC(const float* __restrict__ x) {
    __shared__ int ws[16];
    int b = blockIdx.x, tid = threadIdx.x;
    int i = b * 400 + tid;
    int v = (tid < 400) ? g_cnt[i] : 0;
    int lane = tid & 31, wid = tid >> 5;
    int xc = v;
    for (int d = 1; d < 32; d <<= 1) {
        int n = __shfl_up_sync(FULLMASK, xc, d);
        if (lane >= d) xc += n;
    }
    if (lane == 31) ws[wid] = xc;
    __syncthreads();
    if (wid == 0) {
        int w = (lane < 16) ? ws[lane] : 0;
        for (int d = 1; d < 16; d <<= 1) {
            int n = __shfl_up_sync(FULLMASK, w, d);
            if (lane >= d) w += n;
        }
        if (lane < 16) ws[lane] = w;
    }
    __syncthreads();
    int excl = ((wid > 0) ? ws[wid - 1] : 0) + xc - v + g_boff[b];
    if (tid < 400) {
        g_rowptr[i] = excl;
        g_cursor[i] = excl;
        float dv = rsqrtf((float)(v + 1));   // deg includes self-loop
        g_dinv[i] = dv;
        g_xd[i]   = x[i] * dv;
    }
}

__global__ void k_fill(const int* __restrict__ ei) {
    int e = blockIdx.x * blockDim.x + threadIdx.x;
    if (e < EE) {
        int src = ei[e];
        int dst = ei[EE + e];
        int p = atomicAdd(&g_cursor[dst], 1);
        g_col[p] = src;
    }
}

__device__ __forceinline__ float silu_f(float v) {
    return v / (1.0f + __expf(-v));
}

__device__ __forceinline__ unsigned long long pack2(float a, float b) {
    unsigned long long r;
    asm("mov.b64 %0, {%1, %2};" : "=l"(r) : "f"(a), "f"(b));
    return r;
}
__device__ __forceinline__ unsigned long long fma2(unsigned long long a,
                                                   unsigned long long b,
                                                   unsigned long long c) {
    unsigned long long d;
    asm("fma.rn.f32x2 %0, %1, %2, %3;" : "=l"(d) : "l"(a), "l"(b), "l"(c));
    return d;
}
__device__ __forceinline__ float2 unpack2(unsigned long long v) {
    float2 f;
    asm("mov.b64 {%0, %1}, %2;" : "=f"(f.x), "=f"(f.y) : "l"(v));
    return f;
}

// Layer 1: scalar gather + feature expansion; writes p1 row in {f_l, f_{l+32}} float2 layout
__global__ void k_l1(const float* __restrict__ W1, const float* __restrict__ b1) {
    int w = (blockIdx.x * blockDim.x + threadIdx.x) >> 5;
    int lane = threadIdx.x & 31;
    if (w >= NN) return;
    int d = w;
    int s0 = g_rowptr[d], s1 = g_rowptr[d + 1];
    float s = 0.f;
    for (int j = s0 + lane; j < s1; j += 32) s += g_xd[g_col[j]];
    for (int o = 16; o; o >>= 1) s += __shfl_xor_sync(FULLMASK, s, o);
    float dv = g_dinv[d];
    float a1 = (s + g_xd[d]) * dv;   // self-loop term: xd[d]
    float h0 = fmaf(a1, W1[lane],      b1[lane]);
    float h1 = fmaf(a1, W1[lane + 32], b1[lane + 32]);
    h0 = silu_f(h0);
    h1 = silu_f(h1);
    ((float2*)g_p1)[(d << 5) + lane] = make_float2(h0 * dv, h1 * dv);
}

// Fused layer-2 aggregation + MLP head. Warp handles 4 nodes.
// Aggregation accumulator per lane is float2 {f_lane, f_lane+32} -> directly the
// (lo, hi) layout the shuffle-broadcast GEMV consumes. No intermediate array.
__global__ void __launch_bounds__(256) k_l2mlp(
    const float* __restrict__ W2, const float* __restrict__ b2,
    const float* __restrict__ W3, const float* __restrict__ b3,
    const float* __restrict__ W4, const float* __restrict__ b4,
    float* __restrict__ out)
{
    __shared__ unsigned long long sW2[64][32];
    __shared__ unsigned long long sW3[64][32];
    int tid = threadIdx.x;
    for (int idx = tid; idx < 64 * 32; idx += 256) {
        int k = idx >> 5, l = idx & 31;
        sW2[k][l] = pack2(W2[k * 64 + l], W2[k * 64 + l + 32]);
        sW3[k][l] = pack2(W3[k * 64 + l], W3[k * 64 + l + 32]);
    }
    __syncthreads();

    int lane = tid & 31;
    unsigned long long rb2 = pack2(b2[lane], b2[lane + 32]);
    unsigned long long rb3 = pack2(b3[lane], b3[lane + 32]);
    float w4lo = W4[lane], w4hi = W4[lane + 32];
    float b4v = b4[0];

    int wg = (blockIdx.x * 256 + tid) >> 5;
    int wT = (gridDim.x * 256) >> 5;
    const float2* __restrict__ p = (const float2*)g_p1;

    for (int g = wg; g < NN / 4; g += wT) {
        int d0 = g << 2;
        float lo[4], hi[4];

        // ---- Aggregation: 4 CSR rows, per-lane float2 sums (L2-resident gathers) ----
#pragma unroll
        for (int m = 0; m < 4; m++) {
            int d = d0 + m;
            float2 acc = p[(d << 5) + lane];   // self-loop term p1[d]
            int j = g_rowptr[d], e = g_rowptr[d + 1];
            for (; j + 4 <= e; j += 4) {
                int c0 = g_col[j], c1 = g_col[j + 1], c2 = g_col[j + 2], c3 = g_col[j + 3];
                float2 v0 = p[(c0 << 5) + lane];
                float2 v1 = p[(c1 << 5) + lane];
                float2 v2 = p[(c2 << 5) + lane];
                float2 v3 = p[(c3 << 5) + lane];
                acc.x += (v0.x + v1.x) + (v2.x + v3.x);
                acc.y += (v0.y + v1.y) + (v2.y + v3.y);
            }
            for (; j < e; j++) {
                float2 v = p[(g_col[j] << 5) + lane];
                acc.x += v.x;
                acc.y += v.y;
            }
            float dv = g_dinv[d];
            lo[m] = acc.x * dv;
            hi[m] = acc.y * dv;
        }

        // ---- GEMV 1: a2 @ W2 + b2 ----
        unsigned long long acc0 = rb2, acc1 = rb2, acc2v = rb2, acc3 = rb2;
#pragma unroll
        for (int k = 0; k < 32; k++) {
            unsigned long long wv = sW2[k][lane];
            float t0 = __shfl_sync(FULLMASK, lo[0], k);
            float t1 = __shfl_sync(FULLMASK, lo[1], k);
            float t2 = __shfl_sync(FULLMASK, lo[2], k);
            float t3 = __shfl_sync(FULLMASK, lo[3], k);
            acc0 = fma2(pack2(t0, t0), wv, acc0);
            acc1 = fma2(pack2(t1, t1), wv, acc1);
            acc2v = fma2(pack2(t2, t2), wv, acc2v);
            acc3 = fma2(pack2(t3, t3), wv, acc3);
        }
#pragma unroll
        for (int k = 0; k < 32; k++) {
            unsigned long long wv = sW2[k + 32][lane];
            float t0 = __shfl_sync(FULLMASK, hi[0], k);
            float t1 = __shfl_sync(FULLMASK, hi[1], k);
            float t2 = __shfl_sync(FULLMASK, hi[2], k);
            float t3 = __shfl_sync(FULLMASK, hi[3], k);
            acc0 = fma2(pack2(t0, t0), wv, acc0);
            acc1 = fma2(pack2(t1, t1), wv, acc1);
            acc2v = fma2(pack2(t2, t2), wv, acc2v);
            acc3 = fma2(pack2(t3, t3), wv, acc3);
        }
        {
            float2 a0 = unpack2(acc0), a1 = unpack2(acc1),
                   a2f = unpack2(acc2v), a3 = unpack2(acc3);
            lo[0] = silu_f(a0.x); hi[0] = silu_f(a0.y);
            lo[1] = silu_f(a1.x); hi[1] = silu_f(a1.y);
            lo[2] = silu_f(a2f.x); hi[2] = silu_f(a2f.y);
            lo[3] = silu_f(a3.x); hi[3] = silu_f(a3.y);
        }

        // ---- GEMV 2: h @ W3 + b3 ----
        acc0 = rb3; acc1 = rb3; acc2v = rb3; acc3 = rb3;
#pragma unroll
        for (int k = 0; k < 32; k++) {
            unsigned long long wv = sW3[k][lane];
            float t0 = __shfl_sync(FULLMASK, lo[0], k);
            float t1 = __shfl_sync(FULLMASK, lo[1], k);
            float t2 = __shfl_sync(FULLMASK, lo[2], k);
            float t3 = __shfl_sync(FULLMASK, lo[3], k);
            acc0 = fma2(pack2(t0, t0), wv, acc0);
            acc1 = fma2(pack2(t1, t1), wv, acc1);
            acc2v = fma2(pack2(t2, t2), wv, acc2v);
            acc3 = fma2(pack2(t3, t3), wv, acc3);
        }
#pragma unroll
        for (int k = 0; k < 32; k++) {
            unsigned long long wv = sW3[k + 32][lane];
            float t0 = __shfl_sync(FULLMASK, hi[0], k);
            float t1 = __shfl_sync(FULLMASK, hi[1], k);
            float t2 = __shfl_sync(FULLMASK, hi[2], k);
            float t3 = __shfl_sync(FULLMASK, hi[3], k);
            acc0 = fma2(pack2(t0, t0), wv, acc0);
            acc1 = fma2(pack2(t1, t1), wv, acc1);
            acc2v = fma2(pack2(t2, t2), wv, acc2v);
            acc3 = fma2(pack2(t3, t3), wv, acc3);
        }
        {
            float2 a0 = unpack2(acc0), a1 = unpack2(acc1),
                   a2f = unpack2(acc2v), a3 = unpack2(acc3);
            lo[0] = silu_f(a0.x); hi[0] = silu_f(a0.y);
            lo[1] = silu_f(a1.x); hi[1] = silu_f(a1.y);
            lo[2] = silu_f(a2f.x); hi[2] = silu_f(a2f.y);
            lo[3] = silu_f(a3.x); hi[3] = silu_f(a3.y);
        }

        // ---- Output: dot with W4 ----
#pragma unroll
        for (int m = 0; m < 4; m++) {
            float part = lo[m] * w4lo + hi[m] * w4hi;
            for (int o = 16; o; o >>= 1) part += __shfl_xor_sync(FULLMASK, part, o);
            if (lane == 0) out[d0 + m] = part + b4v;
        }
    }
}

extern "C" void kernel_launch(void* const* d_in, const int* in_sizes, int n_in,
                              void* d_out, int out_size) {
    const float* x  = (const float*)d_in[0];
    const int*   ei = (const int*)d_in[1];
    const float* W1 = (const float*)d_in[2];
    const float* b1 = (const float*)d_in[3];
    const float* W2 = (const float*)d_in[4];
    const float* b2 = (const float*)d_in[5];
    const float* W3 = (const float*)d_in[6];
    const float* b3 = (const float*)d_in[7];
    const float* W4 = (const float*)d_in[8];
    const float* b4 = (const float*)d_in[9];
    float* out = (float*)d_out;

    k_zero <<<(NN + 255) / 256, 256>>>();
    k_count<<<(EE + 255) / 256, 256>>>(ei);
    k_scanA<<<250, 512>>>();
    k_scanB<<<1, 256>>>();
    k_scanC<<<250, 512>>>(x);
    k_fill <<<(EE + 255) / 256, 256>>>(ei);
    k_l1   <<<(NN + 7) / 8, 256>>>(W1, b1);
    k_l2mlp<<<888, 256>>>(W2, b2, W3, b3, W4, b4, out);
}

// round 6
// speedup vs baseline: 1.5424x; 1.1301x over previous
#include <cuda_runtime.h>

#define NN 100000
#define EE 1600000
#define FULLMASK 0xffffffffu

// Scratch (static __device__ arrays per harness rules)
__device__ int   g_cnt[NN];
__device__ int   g_rowptr[NN + 1];
__device__ int   g_cursor[NN];
__device__ int   g_col[EE];
__device__ unsigned long long g_tile[256];   // lookback scan: (state<<32)|sum
__device__ float g_dinv[NN];
__device__ float g_xd[NN];
__device__ float g_p1[NN * 64];   // node d, lane l -> float2 {f_l, f_{l+32}} at ((float2*)g_p1)[d*32+l]

__global__ void k_zero() {
    int i = blockIdx.x * blockDim.x + threadIdx.x;
    if (i < NN) g_cnt[i] = 0;
    if (i < 256) g_tile[i] = 0ULL;
}

__global__ void k_count(const int* __restrict__ ei) {
    int e = blockIdx.x * blockDim.x + threadIdx.x;
    if (e < EE) {
        int dst = ei[EE + e];
        atomicAdd(&g_cnt[dst], 1);
    }
}

// Single-pass decoupled-lookback exclusive scan over g_cnt.
// 196 blocks x 512 threads; also produces cursor, dinv, xd.
__global__ void __launch_bounds__(512) k_scan(const float* __restrict__ x) {
    __shared__ int ws[16];
    __shared__ int s_prefix;
    int b = blockIdx.x, tid = threadIdx.x;
    int lane = tid & 31, wid = tid >> 5;
    int i = b * 512 + tid;
    int v = (i < NN) ? g_cnt[i] : 0;

    // warp inclusive scan
    int xc = v;
    for (int d = 1; d < 32; d <<= 1) {
        int n = __shfl_up_sync(FULLMASK, xc, d);
        if (lane >= d) xc += n;
    }
    if (lane == 31) ws[wid] = xc;
    __syncthreads();
    if (wid == 0) {
        int w = (lane < 16) ? ws[lane] : 0;
        for (int d = 1; d < 16; d <<= 1) {
            int n = __shfl_up_sync(FULLMASK, w, d);
            if (lane >= d) w += n;
        }
        if (lane < 16) ws[lane] = w;
    }
    __syncthreads();
    int excl_local = ((wid > 0) ? ws[wid - 1] : 0) + xc - v;
    int total = ws[15];

    if (tid == 0) {
        if (b == 0) {
            atomicExch(&g_tile[0], (2ULL << 32) | (unsigned)total);
            s_prefix = 0;
        } else {
            atomicExch(&g_tile[b], (1ULL << 32) | (unsigned)total);
            int pref = 0, j = b - 1;
            while (1) {
                unsigned long long t;
                do {
                    t = *((volatile unsigned long long*)&g_tile[j]);
                } while ((t >> 32) == 0ULL);
                pref += (int)(unsigned)t;
                if ((t >> 32) == 2ULL) break;
                j--;
            }
            atomicExch(&g_tile[b], (2ULL << 32) | (unsigned)(pref + total));
            s_prefix = pref;
        }
    }
    __syncthreads();
    int excl = s_prefix + excl_local;
    if (i < NN) {
        g_rowptr[i] = excl;
        g_cursor[i] = excl;
        float dv = rsqrtf((float)(v + 1));   // deg includes self-loop
        g_dinv[i] = dv;
        g_xd[i]   = x[i] * dv;
    }
    if (b == 0 && tid == 0) g_rowptr[NN] = EE;
}

__global__ void k_fill(const int* __restrict__ ei) {
    int e = blockIdx.x * blockDim.x + threadIdx.x;
    if (e < EE) {
        int src = ei[e];
        int dst = ei[EE + e];
        int p = atomicAdd(&g_cursor[dst], 1);
        g_col[p] = src;
    }
}

__device__ __forceinline__ float silu_f(float v) {
    return v / (1.0f + __expf(-v));
}

__device__ __forceinline__ unsigned long long pack2(float a, float b) {
    unsigned long long r;
    asm("mov.b64 %0, {%1, %2};" : "=l"(r) : "f"(a), "f"(b));
    return r;
}
__device__ __forceinline__ unsigned long long fma2(unsigned long long a,
                                                   unsigned long long b,
                                                   unsigned long long c) {
    unsigned long long d;
    asm("fma.rn.f32x2 %0, %1, %2, %3;" : "=l"(d) : "l"(a), "l"(b), "l"(c));
    return d;
}
__device__ __forceinline__ float2 unpack2(unsigned long long v) {
    float2 f;
    asm("mov.b64 {%0, %1}, %2;" : "=f"(f.x), "=f"(f.y) : "l"(v));
    return f;
}

// Layer 1: scalar gather + feature expansion; writes p1 row in {f_l, f_{l+32}} float2 layout
__global__ void k_l1(const float* __restrict__ W1, const float* __restrict__ b1) {
    int w = (blockIdx.x * blockDim.x + threadIdx.x) >> 5;
    int lane = threadIdx.x & 31;
    if (w >= NN) return;
    int d = w;
    int s0 = g_rowptr[d], s1 = g_rowptr[d + 1];
    float s = 0.f;
    for (int j = s0 + lane; j < s1; j += 32) s += g_xd[g_col[j]];
    for (int o = 16; o; o >>= 1) s += __shfl_xor_sync(FULLMASK, s, o);
    float dv = g_dinv[d];
    float a1 = (s + g_xd[d]) * dv;   // self-loop term: xd[d]
    float h0 = fmaf(a1, W1[lane],      b1[lane]);
    float h1 = fmaf(a1, W1[lane + 32], b1[lane + 32]);
    h0 = silu_f(h0);
    h1 = silu_f(h1);
    ((float2*)g_p1)[(d << 5) + lane] = make_float2(h0 * dv, h1 * dv);
}

// Fused layer-2 aggregation + MLP head. Warp handles 4 nodes.
// MLP uses k-split f32x2 GEMVs: activations staged in smem as {t_k, t_k+32}
// pairs (the aggregation accumulator's native layout), broadcast-LDS per k-iter;
// weights pre-packed as {W[k][j], W[k+32][j]}. No SHFL in the hot loop.
__global__ void __launch_bounds__(256) k_l2mlp(
    const float* __restrict__ W2, const float* __restrict__ b2,
    const float* __restrict__ W3, const float* __restrict__ b3,
    const float* __restrict__ W4, const float* __restrict__ b4,
    float* __restrict__ out)
{
    __shared__ unsigned long long sW2kp[32][64];
    __shared__ unsigned long long sW3kp[32][64];
    __shared__ unsigned long long tsm[8][4][32];
    int tid = threadIdx.x;
    for (int idx = tid; idx < 32 * 64; idx += 256) {
        int k = idx >> 6, j = idx & 63;
        sW2kp[k][j] = pack2(W2[k * 64 + j], W2[(k + 32) * 64 + j]);
        sW3kp[k][j] = pack2(W3[k * 64 + j], W3[(k + 32) * 64 + j]);
    }
    __syncthreads();

    int lane = tid & 31, w = tid >> 5;
    float b2lo = b2[lane], b2hi = b2[lane + 32];
    float b3lo = b3[lane], b3hi = b3[lane + 32];
    float w4lo = W4[lane], w4hi = W4[lane + 32];
    float b4v = b4[0];

    const float2* __restrict__ p = (const float2*)g_p1;
    int wg = (blockIdx.x * 256 + tid) >> 5;
    int wT = (gridDim.x * 256) >> 5;

    for (int g = wg; g < NN / 4; g += wT) {
        int d0 = g << 2;
        __syncwarp();   // previous iteration's GEMV2 reads of tsm are done

        // ---- Aggregation: 4 CSR rows -> tsm[w][m][lane] = {a_l, a_l+32} ----
#pragma unroll
        for (int m = 0; m < 4; m++) {
            int d = d0 + m;
            float2 acc = p[(d << 5) + lane];   // self-loop term p1[d]
            int j = g_rowptr[d], e = g_rowptr[d + 1];
            for (; j + 4 <= e; j += 4) {
                int c0 = g_col[j], c1 = g_col[j + 1], c2 = g_col[j + 2], c3 = g_col[j + 3];
                float2 v0 = p[(c0 << 5) + lane];
                float2 v1 = p[(c1 << 5) + lane];
                float2 v2 = p[(c2 << 5) + lane];
                float2 v3 = p[(c3 << 5) + lane];
                acc.x += (v0.x + v1.x) + (v2.x + v3.x);
                acc.y += (v0.y + v1.y) + (v2.y + v3.y);
            }
            for (; j < e; j++) {
                float2 v = p[(g_col[j] << 5) + lane];
                acc.x += v.x;
                acc.y += v.y;
            }
            float dv = g_dinv[d];
            tsm[w][m][lane] = pack2(acc.x * dv, acc.y * dv);
        }
        __syncwarp();

        // ---- GEMV 1: t @ W2 + b2 (k-split) ----
        unsigned long long accA[4], accB[4];
#pragma unroll
        for (int m = 0; m < 4; m++) {
            accA[m] = pack2(b2lo, 0.f);
            accB[m] = pack2(b2hi, 0.f);
        }
#pragma unroll
        for (int k = 0; k < 32; k++) {
            unsigned long long wA = sW2kp[k][lane];
            unsigned long long wB = sW2kp[k][lane + 32];
#pragma unroll
            for (int m = 0; m < 4; m++) {
                unsigned long long tv = tsm[w][m][k];
                accA[m] = fma2(tv, wA, accA[m]);
                accB[m] = fma2(tv, wB, accB[m]);
            }
        }
        __syncwarp();
        {
#pragma unroll
            for (int m = 0; m < 4; m++) {
                float2 a = unpack2(accA[m]);
                float2 bq = unpack2(accB[m]);
                float hlo = silu_f(a.x + a.y);
                float hhi = silu_f(bq.x + bq.y);
                tsm[w][m][lane] = pack2(hlo, hhi);
            }
        }
        __syncwarp();

        // ---- GEMV 2: h @ W3 + b3 (k-split) ----
#pragma unroll
        for (int m = 0; m < 4; m++) {
            accA[m] = pack2(b3lo, 0.f);
            accB[m] = pack2(b3hi, 0.f);
        }
#pragma unroll
        for (int k = 0; k < 32; k++) {
            unsigned long long wA = sW3kp[k][lane];
            unsigned long long wB = sW3kp[k][lane + 32];
#pragma unroll
            for (int m = 0; m < 4; m++) {
                unsigned long long tv = tsm[w][m][k];
                accA[m] = fma2(tv, wA, accA[m]);
                accB[m] = fma2(tv, wB, accB[m]);
            }
        }

        // ---- Output: silu + dot with W4 ----
#pragma unroll
        for (int m = 0; m < 4; m++) {
            float2 a = unpack2(accA[m]);
            float2 bq = unpack2(accB[m]);
            float hlo = silu_f(a.x + a.y);
            float hhi = silu_f(bq.x + bq.y);
            float part = hlo * w4lo + hhi * w4hi;
            for (int o = 16; o; o >>= 1) part += __shfl_xor_sync(FULLMASK, part, o);
            if (lane == 0) out[d0 + m] = part + b4v;
        }
    }
}

extern "C" void kernel_launch(void* const* d_in, const int* in_sizes, int n_in,
                              void* d_out, int out_size) {
    const float* x  = (const float*)d_in[0];
    const int*   ei = (const int*)d_in[1];
    const float* W1 = (const float*)d_in[2];
    const float* b1 = (const float*)d_in[3];
    const float* W2 = (const float*)d_in[4];
    const float* b2 = (const float*)d_in[5];
    const float* W3 = (const float*)d_in[6];
    const float* b3 = (const float*)d_in[7];
    const float* W4 = (const float*)d_in[8];
    const float* b4 = (const float*)d_in[9];
    float* out = (float*)d_out;

    k_zero <<<(NN + 255) / 256, 256>>>();
    k_count<<<(EE + 255) / 256, 256>>>(ei);
    k_scan <<<196, 512>>>(x);
    k_fill <<<(EE + 255) / 256, 256>>>(ei);
    k_l1   <<<(NN + 7) / 8, 256>>>(W1, b1);
    k_l2mlp<<<888, 256>>>(W2, b2, W3, b3, W4, b4, out);
}